// round 2
// baseline (speedup 1.0000x reference)
#include <cuda_runtime.h>
#include <stdint.h>

#define DIM 64
#define NT 1024
#define M_TILE 128
#define N_CHUNK 64
#define TM 8
#define TN 4
#define MAX_Q (64 * 4096)

// Scratch (no device allocation allowed): ids per query + 0.5*||c||^2 per row.
__device__ int   g_ids[MAX_Q];
__device__ float g_hcsq[NT];

// ---------------------------------------------------------------------------
// 1) 0.5 * ||c||^2 per codebook row
// ---------------------------------------------------------------------------
__global__ void csq_kernel(const float* __restrict__ cb) {
    int c = blockIdx.x * blockDim.x + threadIdx.x;
    if (c < NT) {
        const float4* row = (const float4*)(cb + (size_t)c * DIM);
        float s = 0.f;
#pragma unroll
        for (int i = 0; i < DIM / 4; i++) {
            float4 v = row[i];
            s += v.x * v.x + v.y * v.y + v.z * v.z + v.w * v.w;
        }
        g_hcsq[c] = 0.5f * s;
    }
}

// ---------------------------------------------------------------------------
// 2) Main argmax(x.c - 0.5*||c||^2) kernel.
//    CTA: 128 queries x 1024 codes (16 chunks of 64). 256 threads = 16x16.
//    Thread tile: TM=8 queries x TN=4 codes -> 32 FFMA per k-step.
//    Static smem = 32KB + 16KB = 48KB exactly (fits 0xC000 limit).
// ---------------------------------------------------------------------------
__global__ __launch_bounds__(256, 2)
void vq_kernel(const float* __restrict__ codes, const float* __restrict__ cb) {
    __shared__ float sA[DIM][M_TILE];   // [k][m] queries, 32 KB
    __shared__ float sB[DIM][N_CHUNK];  // [k][n] codes,   16 KB

    const int tid = threadIdx.x;
    const int tx = tid & 15;            // code dim
    const int ty = tid >> 4;            // query dim
    const int qbase = blockIdx.x * M_TILE;

    // Load query tile (transposed to k-major): 2048 float4, 8 per thread.
#pragma unroll
    for (int i = tid; i < M_TILE * DIM / 4; i += 256) {
        int m  = i / (DIM / 4);
        int kk = (i % (DIM / 4)) * 4;
        float4 v = *(const float4*)(codes + (size_t)(qbase + m) * DIM + kk);
        sA[kk + 0][m] = v.x; sA[kk + 1][m] = v.y;
        sA[kk + 2][m] = v.z; sA[kk + 3][m] = v.w;
    }

    float bestv[TM];
    int   besti[TM];
#pragma unroll
    for (int i = 0; i < TM; i++) { bestv[i] = -1e30f; besti[i] = 0; }

    for (int c0 = 0; c0 < NT; c0 += N_CHUNK) {
        __syncthreads();  // protect sB from previous iteration's readers
        // Load codebook chunk (transposed): 1024 float4, 4 per thread.
#pragma unroll
        for (int i = tid; i < N_CHUNK * DIM / 4; i += 256) {
            int n  = i / (DIM / 4);
            int kk = (i % (DIM / 4)) * 4;
            float4 v = *(const float4*)(cb + (size_t)(c0 + n) * DIM + kk);
            sB[kk + 0][n] = v.x; sB[kk + 1][n] = v.y;
            sB[kk + 2][n] = v.z; sB[kk + 3][n] = v.w;
        }
        __syncthreads();

        float acc[TM][TN];
#pragma unroll
        for (int i = 0; i < TM; i++)
#pragma unroll
            for (int j = 0; j < TN; j++) acc[i][j] = 0.f;

#pragma unroll 8
        for (int k = 0; k < DIM; k++) {
            float a[TM], b[TN];
#pragma unroll
            for (int i = 0; i < TM; i++) a[i] = sA[k][ty * TM + i];
#pragma unroll
            for (int j = 0; j < TN; j++) b[j] = sB[k][tx * TN + j];
#pragma unroll
            for (int i = 0; i < TM; i++)
#pragma unroll
                for (int j = 0; j < TN; j++) acc[i][j] += a[i] * b[j];
        }

        // Running best (strict > keeps the FIRST max; per-thread code idx is
        // strictly increasing over the loop, matching jnp.argmin tie-break).
#pragma unroll
        for (int j = 0; j < TN; j++) {
            int idx = c0 + tx * TN + j;
            float hcs = __ldg(&g_hcsq[idx]);   // L2-resident, 64 values/chunk
#pragma unroll
            for (int i = 0; i < TM; i++) {
                float score = acc[i][j] - hcs;
                if (score > bestv[i]) { bestv[i] = score; besti[i] = idx; }
            }
        }
    }

    // Cross-thread (tx) reduction per query, lexicographic (val desc, idx asc).
    __syncthreads();
    float* rv = &sA[0][0];       // 128*16 floats (8 KB of sA)
    int*   ri = (int*)&sB[0][0]; // 128*16 ints   (8 KB of sB)
#pragma unroll
    for (int i = 0; i < TM; i++) {
        int m = ty * TM + i;
        rv[m * 16 + tx] = bestv[i];
        ri[m * 16 + tx] = besti[i];
    }
    __syncthreads();
    if (tid < M_TILE) {
        float bv = rv[tid * 16 + 0];
        int   bi = ri[tid * 16 + 0];
#pragma unroll
        for (int t = 1; t < 16; t++) {
            float v  = rv[tid * 16 + t];
            int   ii = ri[tid * 16 + t];
            if (v > bv || (v == bv && ii < bi)) { bv = v; bi = ii; }
        }
        g_ids[qbase + tid] = bi;
    }
}

// ---------------------------------------------------------------------------
// 3) Gather codebook[best] -> out_codes; optionally write ids (as float).
// ---------------------------------------------------------------------------
__global__ void gather_kernel(const float* __restrict__ cb,
                              float* __restrict__ out_codes,
                              float* __restrict__ out_ids,
                              int nq, int write_ids) {
    int t = blockIdx.x * blockDim.x + threadIdx.x;  // one per float4
    if (t < nq * (DIM / 4)) {
        int q    = t >> 4;
        int part = t & 15;
        int id   = g_ids[q];
        float4 v = *(const float4*)(cb + (size_t)id * DIM + part * 4);
        *(float4*)(out_codes + (size_t)q * DIM + part * 4) = v;
    }
    if (write_ids && t < nq) out_ids[t] = (float)g_ids[t];
}

// ---------------------------------------------------------------------------
extern "C" void kernel_launch(void* const* d_in, const int* in_sizes, int n_in,
                              void* d_out, int out_size) {
    const float* codes = (const float*)d_in[0];
    const float* cb    = (const float*)d_in[1];
    float* out = (float*)d_out;

    int nq = in_sizes[0] / DIM;          // 262144 expected
    if (nq > MAX_Q) nq = MAX_Q;

    csq_kernel<<<(NT + 255) / 256, 256>>>(cb);
    vq_kernel<<<nq / M_TILE, 256>>>(codes, cb);

    // Output layout guess: [quant_codes nq*DIM][quant_id nq], all float32.
    int write_ids = (out_size >= nq * DIM + nq) ? 1 : 0;
    float* out_ids = out + (size_t)nq * DIM;
    int total = nq * (DIM / 4);
    gather_kernel<<<(total + 255) / 256, 256>>>(cb, out, out_ids, nq, write_ids);
}

// round 4
// speedup vs baseline: 2.2264x; 2.2264x over previous
#include <cuda_runtime.h>
#include <cuda_bf16.h>
#include <stdint.h>

#define DIM 64
#define NT 1024
#define MQ 128                  // queries per CTA
#define NCH 128                 // codes per chunk
#define NCHUNKS (NT / NCH)      // 8
#define MAX_Q (64 * 4096)
#define DELTA 2e-3f             // rescue margin (>> bf16x3 worst-case error)

// ---------------- global scratch (no allocation allowed) ----------------
__device__ int           g_ids[MAX_Q];
__device__ float         g_hcsq[NT];                 // 0.5*||c||^2
__device__ __nv_bfloat16 g_Bhi[NT * DIM];            // codebook hi, swizzled tiles
__device__ __nv_bfloat16 g_Blo[NT * DIM];            // codebook lo, swizzled tiles
__device__ int           g_nrescue;
__device__ int           g_rescue[MAX_Q];

// ---------------- helpers ----------------
__device__ __forceinline__ uint32_t smem_u32(const void* p) {
    uint32_t a;
    asm("{ .reg .u64 t; cvta.to.shared.u64 t, %1; cvt.u32.u64 %0, t; }"
        : "=r"(a) : "l"(p));
    return a;
}
__device__ __forceinline__ void ldm_x4(uint32_t* r, uint32_t addr) {
    asm volatile("ldmatrix.sync.aligned.m8n8.x4.shared.b16 {%0,%1,%2,%3}, [%4];"
                 : "=r"(r[0]), "=r"(r[1]), "=r"(r[2]), "=r"(r[3]) : "r"(addr));
}
__device__ __forceinline__ void mma_bf16(float* c, const uint32_t* a,
                                         uint32_t b0, uint32_t b1) {
    asm volatile(
        "mma.sync.aligned.m16n8k16.row.col.f32.bf16.bf16.f32 "
        "{%0,%1,%2,%3}, {%4,%5,%6,%7}, {%8,%9}, {%0,%1,%2,%3};"
        : "+f"(c[0]), "+f"(c[1]), "+f"(c[2]), "+f"(c[3])
        : "r"(a[0]), "r"(a[1]), "r"(a[2]), "r"(a[3]), "r"(b0), "r"(b1));
}
__device__ __forceinline__ void cpa16(uint32_t dst, const void* src) {
    asm volatile("cp.async.cg.shared.global [%0], [%1], 16;" :: "r"(dst), "l"(src));
}
#define CPA_COMMIT() asm volatile("cp.async.commit_group;" ::: "memory")
#define CPA_WAIT0()  asm volatile("cp.async.wait_group 0;" ::: "memory")

// Tile geometry: 128 rows x 128 bytes (64 bf16). 16B chunk swizzle: c ^= (row&7).
__device__ __forceinline__ uint32_t sw_off(int row, int chunk) {
    return (uint32_t)row * 128u + (uint32_t)((chunk ^ (row & 7)) << 4);
}

// hi/lo bf16 split of a float
__device__ __forceinline__ void split2(float x, __nv_bfloat16& h, __nv_bfloat16& l) {
    h = __float2bfloat16_rn(x);
    l = __float2bfloat16_rn(x - __bfloat162float(h));
}

// ---------------- smem map (dynamic, 102400 B) ----------------
#define SM_AHI 0          // 16 KB
#define SM_ALO 16384      // 16 KB
#define SM_B   32768      // 2 stages x (hi 16KB + lo 16KB) = 64 KB
#define SM_HC  98304      // 4 KB
#define SMEM_TOTAL 102400

// ---------------------------------------------------------------------------
// prep: hcsq, codebook hi/lo split into swizzled chunk-major tiles, reset ctr.
// ---------------------------------------------------------------------------
__global__ void prep_kernel(const float* __restrict__ cb) {
    int t = blockIdx.x * blockDim.x + threadIdx.x;
    if (t == 0) g_nrescue = 0;
    if (t >= NT * 16) return;
    int n = t >> 4, kq = t & 15;                 // kq: float4 index 0..15
    float4 v = *(const float4*)(cb + (size_t)n * DIM + kq * 4);
    __nv_bfloat16 h[4], l[4];
    split2(v.x, h[0], l[0]); split2(v.y, h[1], l[1]);
    split2(v.z, h[2], l[2]); split2(v.w, h[3], l[3]);
    int ch = n >> 7, ln = n & 127;
    uint32_t off = (uint32_t)ch * 16384u + sw_off(ln, kq >> 1) + (kq & 1) * 8;
    *(uint2*)((char*)g_Bhi + off) = *(uint2*)h;
    *(uint2*)((char*)g_Blo + off) = *(uint2*)l;
    if (kq == 0) {
        const float4* row = (const float4*)(cb + (size_t)n * DIM);
        float s = 0.f;
#pragma unroll
        for (int i = 0; i < 16; i++) {
            float4 w = row[i];
            s += w.x * w.x + w.y * w.y + w.z * w.z + w.w * w.w;
        }
        g_hcsq[n] = 0.5f * s;
    }
}

// ---------------------------------------------------------------------------
// main: bf16x3 mma.sync GEMM + running top-2 argmax.
// 8 warps = 2(m) x 4(n); warp tile 64 x 32; full K=64 per chunk.
// ---------------------------------------------------------------------------
__global__ void __launch_bounds__(256, 1)
vq_mma_kernel(const float* __restrict__ codes) {
    extern __shared__ char smem[];
    const uint32_t sb = smem_u32(smem);
    const int tid  = threadIdx.x;
    const int wid  = tid >> 5, lane = tid & 31;
    const int wm   = wid >> 2;           // 0..1 -> m offset 0/64
    const int wn   = wid & 3;            // 0..3 -> n offset 0/32/64/96
    const int qbase = blockIdx.x * MQ;

    // prefetch B chunk 0 -> stage 0
    for (int i = tid; i < 1024; i += 256) {
        cpa16(sb + SM_B + i * 16, (const char*)g_Bhi + i * 16);
        cpa16(sb + SM_B + 16384 + i * 16, (const char*)g_Blo + i * 16);
    }
    CPA_COMMIT();

    // hcsq -> smem
    for (int i = tid; i < NT / 4; i += 256)
        ((float4*)(smem + SM_HC))[i] = ((const float4*)g_hcsq)[i];

    // A tile: load fp32, split hi/lo, store swizzled bf16
    for (int i = tid; i < MQ * 16; i += 256) {
        int m = i >> 4, kq = i & 15;
        float4 v = *(const float4*)(codes + (size_t)(qbase + m) * DIM + kq * 4);
        __nv_bfloat16 h[4], l[4];
        split2(v.x, h[0], l[0]); split2(v.y, h[1], l[1]);
        split2(v.z, h[2], l[2]); split2(v.w, h[3], l[3]);
        uint32_t off = sw_off(m, kq >> 1) + (kq & 1) * 8;
        *(uint2*)(smem + SM_AHI + off) = *(uint2*)h;
        *(uint2*)(smem + SM_ALO + off) = *(uint2*)l;
    }

    float b1[8], b2[8];
    int   i1[8];
#pragma unroll
    for (int r = 0; r < 8; r++) { b1[r] = -1e30f; b2[r] = -1e30f; i1[r] = 0; }

    const float* hc = (const float*)(smem + SM_HC);

    for (int c = 0; c < NCHUNKS; c++) {
        const int st = c & 1;
        CPA_WAIT0();
        __syncthreads();          // chunk c resident; all warps done with prev stage

        if (c + 1 < NCHUNKS) {    // prefetch chunk c+1 into the other stage
            const char* bh = (const char*)g_Bhi + (size_t)(c + 1) * 16384;
            const char* bl = (const char*)g_Blo + (size_t)(c + 1) * 16384;
            uint32_t dst = sb + SM_B + (st ^ 1) * 32768;
            for (int i = tid; i < 1024; i += 256) {
                cpa16(dst + i * 16, bh + i * 16);
                cpa16(dst + 16384 + i * 16, bl + i * 16);
            }
            CPA_COMMIT();
        }

        float acc[4][4][4];
#pragma unroll
        for (int mi = 0; mi < 4; mi++)
#pragma unroll
            for (int nj = 0; nj < 4; nj++)
#pragma unroll
                for (int e = 0; e < 4; e++) acc[mi][nj][e] = 0.f;

        const uint32_t aBaseHi = sb + SM_AHI, aBaseLo = sb + SM_ALO;
        const uint32_t bBaseHi = sb + SM_B + st * 32768;
        const uint32_t bBaseLo = bBaseHi + 16384;

#pragma unroll
        for (int ks = 0; ks < 4; ks++) {
            // A addresses: row = wm*64 + mi*16 + (lane&15); chunk = ks*2 + (lane>>4)
            uint32_t ah[4][4], al[4][4];
#pragma unroll
            for (int mi = 0; mi < 4; mi++) {
                int ra = wm * 64 + mi * 16 + (lane & 15);
                uint32_t off = sw_off(ra, ks * 2 + (lane >> 4));
                ldm_x4(ah[mi], aBaseHi + off);
                ldm_x4(al[mi], aBaseLo + off);
            }
            // B addresses: row = wn*32 + ni2*16 + (lane&7) + ((lane&16)?8:0)
            //              chunk = ks*2 + ((lane>>3)&1)
            uint32_t bh[2][4], bl[2][4];
#pragma unroll
            for (int ni2 = 0; ni2 < 2; ni2++) {
                int rb = wn * 32 + ni2 * 16 + (lane & 7) + ((lane & 16) ? 8 : 0);
                uint32_t off = sw_off(rb, ks * 2 + ((lane >> 3) & 1));
                ldm_x4(bh[ni2], bBaseHi + off);
                ldm_x4(bl[ni2], bBaseLo + off);
            }
#pragma unroll
            for (int mi = 0; mi < 4; mi++)
#pragma unroll
                for (int nj = 0; nj < 4; nj++) {
                    uint32_t h0 = bh[nj >> 1][(nj & 1) * 2];
                    uint32_t h1 = bh[nj >> 1][(nj & 1) * 2 + 1];
                    uint32_t l0 = bl[nj >> 1][(nj & 1) * 2];
                    uint32_t l1 = bl[nj >> 1][(nj & 1) * 2 + 1];
                    mma_bf16(acc[mi][nj], ah[mi], h0, h1);
                    mma_bf16(acc[mi][nj], al[mi], h0, h1);
                    mma_bf16(acc[mi][nj], ah[mi], l0, l1);
                }
        }

        // epilogue: top-2 update. n ascending within each row's scan order.
#pragma unroll
        for (int mi = 0; mi < 4; mi++)
#pragma unroll
            for (int h = 0; h < 2; h++) {
                int ri = mi * 2 + h;
                float v1 = b1[ri], v2 = b2[ri];
                int   ii = i1[ri];
#pragma unroll
                for (int nj = 0; nj < 4; nj++)
#pragma unroll
                    for (int p = 0; p < 2; p++) {
                        int n = c * NCH + wn * 32 + nj * 8 + (lane & 3) * 2 + p;
                        float v = acc[mi][nj][h * 2 + p] - hc[n];
                        bool gt = v > v1;
                        v2 = gt ? v1 : fmaxf(v2, v);
                        ii = gt ? n : ii;
                        v1 = gt ? v : v1;
                    }
                b1[ri] = v1; b2[ri] = v2; i1[ri] = ii;
            }
    }

    // intra-warp merge over the 4 lanes sharing each row (lane bits 0-1)
#pragma unroll
    for (int r = 0; r < 8; r++) {
#pragma unroll
        for (int d = 1; d <= 2; d <<= 1) {
            float ov  = __shfl_xor_sync(0xffffffffu, b1[r], d);
            int   oi  = __shfl_xor_sync(0xffffffffu, i1[r], d);
            float ov2 = __shfl_xor_sync(0xffffffffu, b2[r], d);
            bool take = (ov > b1[r]) || (ov == b1[r] && oi < i1[r]);
            float lose = take ? b1[r] : ov;
            b2[r] = fmaxf(fmaxf(b2[r], ov2), lose);
            if (take) { b1[r] = ov; i1[r] = oi; }
        }
    }

    // cross-warp (wn) merge via smem
    __syncthreads();
    float* rv  = (float*)(smem + SM_AHI);          // [128][4]
    int*   rix = (int*)(smem + SM_AHI + 2048);     // [128][4]
    float* r2  = (float*)(smem + SM_AHI + 4096);   // [128][4]
    if ((lane & 3) == 0) {
#pragma unroll
        for (int mi = 0; mi < 4; mi++)
#pragma unroll
            for (int h = 0; h < 2; h++) {
                int r = mi * 2 + h;
                int row = wm * 64 + mi * 16 + h * 8 + (lane >> 2);
                rv[row * 4 + wn] = b1[r];
                rix[row * 4 + wn] = i1[r];
                r2[row * 4 + wn] = b2[r];
            }
    }
    __syncthreads();
    if (tid < MQ) {
        float bv = rv[tid * 4], bb2 = r2[tid * 4];
        int   bi = rix[tid * 4];
#pragma unroll
        for (int w = 1; w < 4; w++) {
            float ov = rv[tid * 4 + w], ov2 = r2[tid * 4 + w];
            int   oi = rix[tid * 4 + w];
            bool take = (ov > bv) || (ov == bv && oi < bi);
            float lose = take ? bv : ov;
            bb2 = fmaxf(fmaxf(bb2, ov2), lose);
            if (take) { bv = ov; bi = oi; }
        }
        g_ids[qbase + tid] = bi;
        if (bv - bb2 < DELTA) {
            int r = atomicAdd(&g_nrescue, 1);
            g_rescue[r] = qbase + tid;
        }
    }
}

// ---------------------------------------------------------------------------
// rescue: exact fp32 rescan; 8 queries share one codebook sweep per block.
// ---------------------------------------------------------------------------
#define QB 8
__global__ void rescue_kernel(const float* __restrict__ codes,
                              const float* __restrict__ cb) {
    __shared__ float sx[QB][DIM];
    __shared__ float sv[QB][256];
    __shared__ int   si[QB][256];
    int nres = g_nrescue;
    for (int base = blockIdx.x * QB; base < nres; base += gridDim.x * QB) {
        int cnt = min(QB, nres - base);
        __syncthreads();
        for (int i = threadIdx.x; i < cnt * 16; i += 256) {
            int q = i >> 4, kq = i & 15;
            ((float4*)sx[q])[kq] =
                ((const float4*)(codes + (size_t)g_rescue[base + q] * DIM))[kq];
        }
        __syncthreads();
        float bv[QB]; int bi[QB];
#pragma unroll
        for (int q = 0; q < QB; q++) { bv[q] = -1e30f; bi[q] = 0; }
        for (int j = 0; j < 4; j++) {
            int n = threadIdx.x + j * 256;
            const float* cr = cb + (size_t)n * DIM;
            float dot[QB];
#pragma unroll
            for (int q = 0; q < QB; q++) dot[q] = 0.f;
#pragma unroll
            for (int k = 0; k < DIM; k++) {
                float ck = __ldg(&cr[k]);
#pragma unroll
                for (int q = 0; q < QB; q++) dot[q] += sx[q][k] * ck;
            }
            float hc = g_hcsq[n];
#pragma unroll
            for (int q = 0; q < QB; q++) {
                float s = dot[q] - hc;
                if (s > bv[q]) { bv[q] = s; bi[q] = n; }
            }
        }
#pragma unroll
        for (int q = 0; q < QB; q++) { sv[q][threadIdx.x] = bv[q]; si[q][threadIdx.x] = bi[q]; }
        __syncthreads();
        int w = threadIdx.x >> 5, lane = threadIdx.x & 31;
        if (w < QB && w < cnt) {
            float v = sv[w][lane]; int ix = si[w][lane];
            for (int t = lane + 32; t < 256; t += 32) {
                float ov = sv[w][t]; int oi = si[w][t];
                if (ov > v || (ov == v && oi < ix)) { v = ov; ix = oi; }
            }
#pragma unroll
            for (int d = 16; d > 0; d >>= 1) {
                float ov = __shfl_down_sync(0xffffffffu, v, d);
                int   oi = __shfl_down_sync(0xffffffffu, ix, d);
                if (ov > v || (ov == v && oi < ix)) { v = ov; ix = oi; }
            }
            if (lane == 0) g_ids[g_rescue[base + w]] = ix;
        }
        __syncthreads();
    }
}

// ---------------------------------------------------------------------------
// gather: codebook[best] -> out_codes; ids as float.
// ---------------------------------------------------------------------------
__global__ void gather_kernel(const float* __restrict__ cb,
                              float* __restrict__ out_codes,
                              float* __restrict__ out_ids,
                              int nq, int write_ids) {
    int t = blockIdx.x * blockDim.x + threadIdx.x;
    if (t < nq * (DIM / 4)) {
        int q = t >> 4, part = t & 15;
        int id = g_ids[q];
        float4 v = *(const float4*)(cb + (size_t)id * DIM + part * 4);
        *(float4*)(out_codes + (size_t)q * DIM + part * 4) = v;
    }
    if (write_ids && t < nq) out_ids[t] = (float)g_ids[t];
}

// ---------------------------------------------------------------------------
extern "C" void kernel_launch(void* const* d_in, const int* in_sizes, int n_in,
                              void* d_out, int out_size) {
    const float* codes = (const float*)d_in[0];
    const float* cb    = (const float*)d_in[1];
    float* out = (float*)d_out;

    int nq = in_sizes[0] / DIM;
    if (nq > MAX_Q) nq = MAX_Q;

    static int attr_done = 0;
    if (!attr_done) {
        cudaFuncSetAttribute(vq_mma_kernel,
                             cudaFuncAttributeMaxDynamicSharedMemorySize, SMEM_TOTAL);
        attr_done = 1;
    }

    prep_kernel<<<(NT * 16 + 255) / 256, 256>>>(cb);
    vq_mma_kernel<<<nq / MQ, 256, SMEM_TOTAL>>>(codes);
    rescue_kernel<<<256, 256>>>(codes, cb);

    int write_ids = (out_size >= nq * DIM + nq) ? 1 : 0;
    float* out_ids = out + (size_t)nq * DIM;
    int total = nq * (DIM / 4);
    gather_kernel<<<(total + 255) / 256, 256>>>(cb, out, out_ids, nq, write_ids);
}